// round 13
// baseline (speedup 1.0000x reference)
#include <cuda_runtime.h>
#include <cuda_fp16.h>
#include <cstdint>

// Problem constants
#define Bn   4
#define Sn   96
#define Nn   512
#define Dn   8
#define Hn   64
#define OUTn 24

#define ROWS 16
#define TPB  512             // 16 warps
#define NTIL 32              // Nn/ROWS (CTAs per batch)
#define GRID_CTAS 128
#define KC   32              // K chunks of 16 (Nn/16)

// smem layout (u32/float units)
#define SM_AHI 0             // 4224  : A-frag (fp16 hi only) [(kc*33+lane)*4 + i]
#define SM_W   4224          // 20480 : W fragments (5120 uint4)
#define SM_AH0 24704         // 1280  : ah partial (half 0 + x half 0)  (16 x 80)
#define SM_AH1 25984         // 1280  : ah partial (half 1 + x half 1)
#define SM_HS  27264         // 1024  : h_new scratch
#define SM_EX  28288         // 3072  : o/gg exchange (8 warps x 32 lanes x stride 12)
#define EX_STRIDE 12
#define SMEM_FLOATS 31360
#define SMEM_BYTES  (SMEM_FLOATS * 4)

// ---------------- persistent device state ----------------
__device__ uint4 d_Ffrag[2 * Bn * KC * 8 * 32];   // h frags (fp16 hi/lo), dbl-buffered
__device__ uint4 d_Xfrag[Sn * Bn * KC * 32];      // x frags (fp16 hi/lo), all steps
__device__ uint4 d_Wfrag4[5 * 32 * 32];           // W frags (fp16 hi/lo)
__device__ float  d_hfinal[Bn * Hn];
__device__ __align__(128) unsigned d_flags[Bn * 32];  // per-batch barrier flags (1 line/batch)
__device__ unsigned d_gcnt;
__device__ unsigned d_gflag;

// ---------------- helpers ----------------
__device__ __forceinline__ unsigned fcvt2(float x, float y) {
    __half2 hb = __float22half2_rn(make_float2(x, y));
    return *reinterpret_cast<unsigned*>(&hb);
}
__device__ __forceinline__ void fsplit2(float x, float y, unsigned& h, unsigned& l) {
    __half2 hb = __float22half2_rn(make_float2(x, y));
    float2 hf = __half22float2(hb);
    __half2 lb = __float22half2_rn(make_float2(x - hf.x, y - hf.y));
    h = *reinterpret_cast<unsigned*>(&hb);
    l = *reinterpret_cast<unsigned*>(&lb);
}

__device__ __forceinline__ void mma_f16(float c[4],
                                        unsigned a0, unsigned a1, unsigned a2, unsigned a3,
                                        unsigned b0, unsigned b1) {
    asm volatile(
        "mma.sync.aligned.m16n8k16.row.col.f32.f16.f16.f32 "
        "{%0,%1,%2,%3}, {%4,%5,%6,%7}, {%8,%9}, {%0,%1,%2,%3};\n"
        : "+f"(c[0]), "+f"(c[1]), "+f"(c[2]), "+f"(c[3])
        : "r"(a0), "r"(a1), "r"(a2), "r"(a3), "r"(b0), "r"(b1));
}

__device__ __forceinline__ float sigmoidf_fast(float x) { return 1.0f / (1.0f + __expf(-x)); }
__device__ __forceinline__ float tanhf_fast(float x)    { return 1.0f - 2.0f / (__expf(2.0f * x) + 1.0f); }

// per-batch flag barrier: zero atomics, tight spin on one 128B line
__device__ __forceinline__ void b_barrier(int b, int kcCTA, unsigned epoch) {
    __syncthreads();                                  // sync3: all STG/STS of this step done
    if (threadIdx.x == 0) {
        __threadfence();
        *(volatile unsigned*)&d_flags[b * 32 + kcCTA] = epoch;
    }
    if (threadIdx.x < 32) {
        volatile unsigned* f = d_flags + b * 32;
        while (f[threadIdx.x] < epoch) { }
        __threadfence();                              // acquire side
    }
    __syncthreads();                                  // sync4: release all warps
}

__device__ __forceinline__ void g_barrier() {
    __syncthreads();
    if (threadIdx.x == 0) {
        __threadfence();
        unsigned old = atomicAdd(&d_gcnt, 1u);
        if (old == GRID_CTAS - 1u) {
            asm volatile("st.release.gpu.u32 [%0], %1;" :: "l"(&d_gflag), "r"(1u) : "memory");
        } else {
            unsigned v;
            do {
                asm volatile("ld.acquire.gpu.u32 %0, [%1];" : "=r"(v) : "l"(&d_gflag) : "memory");
            } while (v < 1u);
        }
    }
    __syncthreads();
}

// ---------------- init ----------------
__global__ void init_kernel(const float* __restrict__ x,
                            const float* __restrict__ h0,
                            const float* __restrict__ Wx,
                            const float* __restrict__ Wh) {
    int idx = blockIdx.x * blockDim.x + threadIdx.x;
    if (idx < Bn * 32) d_flags[idx] = 0;
    if (idx == 0) { d_gcnt = 0; d_gflag = 0; }

    if (idx < 5 * 32 * 32) {
        int kk    = idx >> 10;
        int rem   = idx & 1023;
        int ntile = rem >> 5;
        int lane  = rem & 31;
        int g = lane >> 2, tig = lane & 3;
        int col = ntile * 8 + g;
        auto wval = [&](int kr) -> float {
            if (kr >= 72) return 0.0f;
            return (kr < Dn) ? Wx[kr * 256 + col] : Wh[(kr - Dn) * 256 + col];
        };
        int k0 = kk * 16 + 2 * tig;
        unsigned b0h, b0l, b1h, b1l;
        fsplit2(wval(k0),     wval(k0 + 1), b0h, b0l);
        fsplit2(wval(k0 + 8), wval(k0 + 9), b1h, b1l);
        d_Wfrag4[idx] = make_uint4(b0h, b1h, b0l, b1l);
    }

    if (idx < Bn * KC * 8 * 32) {
        int lane = idx & 31;
        int j    = (idx >> 5) & 7;
        int kc   = (idx >> 8) & 31;
        int b    = idx >> 13;
        int g = lane >> 2, tg = lane & 3;
        int col = j * 8 + g;
        const float* hb = h0 + (size_t)b * Nn * Hn;
        float v0 = hb[(kc * 16 + 2 * tg) * Hn + col];
        float v1 = hb[(kc * 16 + 2 * tg + 1) * Hn + col];
        float v2 = hb[(kc * 16 + 2 * tg + 8) * Hn + col];
        float v3 = hb[(kc * 16 + 2 * tg + 9) * Hn + col];
        unsigned b0h, b0l, b1h, b1l;
        fsplit2(v0, v1, b0h, b0l);
        fsplit2(v2, v3, b1h, b1l);
        d_Ffrag[((size_t)b * KC + kc) * 256 + j * 32 + lane] = make_uint4(b0h, b1h, b0l, b1l);
    }

    if (idx < Sn * Bn * KC * 32) {
        int lane = idx & 31;
        int kc   = (idx >> 5) & 31;
        int b    = (idx >> 10) & 3;
        int t    = idx >> 12;
        int g = lane >> 2, tg = lane & 3;
        const float* xs = x + ((size_t)b * Sn + t) * Nn * Dn;
        float v0 = xs[(kc * 16 + 2 * tg) * Dn + g];
        float v1 = xs[(kc * 16 + 2 * tg + 1) * Dn + g];
        float v2 = xs[(kc * 16 + 2 * tg + 8) * Dn + g];
        float v3 = xs[(kc * 16 + 2 * tg + 9) * Dn + g];
        unsigned b0h, b0l, b1h, b1l;
        fsplit2(v0, v1, b0h, b0l);
        fsplit2(v2, v3, b1h, b1l);
        d_Xfrag[(((size_t)t * Bn + b) * KC + kc) * 32 + lane] = make_uint4(b0h, b1h, b0l, b1l);
    }
}

// ---------------- A-tile staging helper (fp16 hi only) ----------------
__device__ __forceinline__ void stage_sts_one(unsigned* __restrict__ usm, int idx, float4 v) {
    int n  = idx >> 7;
    int mq = idx & 127;
    int kc = mq >> 2;
    int k  = (mq & 3) * 4;
    int i  = ((n >> 3) & 1) + 2 * ((k >> 3) & 1);
    int l  = ((n & 7) << 2) | ((k >> 1) & 3);
    usm[SM_AHI + (kc * 33 + l)     * 4 + i] = fcvt2(v.x, v.y);
    usm[SM_AHI + (kc * 33 + l + 1) * 4 + i] = fcvt2(v.z, v.w);
}

// ---------------- the persistent kernel ----------------
__global__ void __launch_bounds__(TPB, 1) persistent_kernel(
    const float* __restrict__ adj,
    const float* __restrict__ c0,
    const float* __restrict__ b_gates,
    const float* __restrict__ W1, const float* __restrict__ b1,
    const float* __restrict__ W2, const float* __restrict__ b2,
    float* __restrict__ out)
{
    extern __shared__ float smem[];
    unsigned* usm = reinterpret_cast<unsigned*>(smem);
    float* ah0 = smem + SM_AH0;
    float* ah1 = smem + SM_AH1;
    float* hs  = smem + SM_HS;
    float* ex  = smem + SM_EX;
    uint4* Wsm = reinterpret_cast<uint4*>(smem + SM_W);

    const int b     = blockIdx.y;
    const int kcCTA = blockIdx.x;
    const int n0    = kcCTA * ROWS;
    const int tid   = threadIdx.x;
    const int lane  = tid & 31;
    const int w     = tid >> 5;           // 0..15
    const int wj    = w & 7;              // phase-1 j tile; phase-2 column slice
    const int half  = w >> 3;             // phase-1 K half; phase-2 gate segment
    const int g     = lane >> 2;
    const int tig   = lane & 3;
    const int colb  = 8 * wj + 2 * tig;
    const bool gate_warp = (half == 0);

    // ---- prologue ----
    for (int i = tid; i < 5 * 32 * 32; i += TPB) Wsm[i] = d_Wfrag4[i];
    for (int e = tid; e < 2 * 1280; e += TPB) (smem + SM_AH0)[e] = 0.0f;

    float creg[4] = {0.f, 0.f, 0.f, 0.f};
    float bgr[4][2];
    if (gate_warp) {
        creg[0] = c0[((size_t)b * Nn + n0 + g) * Hn + colb];
        creg[1] = c0[((size_t)b * Nn + n0 + g) * Hn + colb + 1];
        creg[2] = c0[((size_t)b * Nn + n0 + 8 + g) * Hn + colb];
        creg[3] = c0[((size_t)b * Nn + n0 + 8 + g) * Hn + colb + 1];
        #pragma unroll
        for (int q = 0; q < 4; ++q) {
            bgr[q][0] = b_gates[q * 64 + colb];
            bgr[q][1] = b_gates[q * 64 + colb + 1];
        }
    }

    // stage A for t = 0 (all threads)
    {
        const float* Abase = adj + (((size_t)b * Sn + 0) * Nn + n0) * Nn;
        #pragma unroll
        for (int r = 0; r < 4; ++r) {
            int idx = tid + r * TPB;
            int n = idx >> 7, mq = idx & 127;
            float4 v = *(const float4*)(Abase + (size_t)n * Nn + (size_t)mq * 4);
            stage_sts_one(usm, idx, v);
        }
    }
    __syncthreads();

    for (int t = 0; t < Sn; ++t) {
        const int par = t & 1;
        const float* Anext = adj + (((size_t)b * Sn + (t + 1)) * Nn + n0) * Nn;

        // ---- issue next-adj LDGs (all warps; in flight through phase 1) ----
        float4 av[4];
        if (t < Sn - 1) {
            #pragma unroll
            for (int r = 0; r < 4; ++r) {
                int idx = tid + r * TPB;
                int n = idx >> 7, mq = idx & 127;
                av[r] = *(const float4*)(Anext + (size_t)n * Nn + (size_t)mq * 4);
            }
        }

        // ================= Phase 1 (fp16 2-pass) =================
        const uint4* fb = d_Ffrag + (size_t)(par * Bn + b) * (KC * 8 * 32) + wj * 32 + lane;
        const int kbase = half * 16;
        uint4 q[4], qn[4];
        #pragma unroll
        for (int u = 0; u < 4; ++u) q[u] = fb[(size_t)(kbase + u) * 256];

        const uint4* xb = d_Xfrag + (size_t)(t * Bn + b) * (KC * 32) + lane;
        uint4 xq0 = xb[(size_t)(2 * w) * 32];
        uint4 xq1 = xb[(size_t)(2 * w + 1) * 32];

        float acch[2][2][4], accx[2][4];
        #pragma unroll
        for (int s = 0; s < 2; ++s)
            #pragma unroll
            for (int p = 0; p < 2; ++p)
                #pragma unroll
                for (int i = 0; i < 4; ++i) acch[s][p][i] = 0.0f;
        #pragma unroll
        for (int p = 0; p < 2; ++p)
            #pragma unroll
            for (int i = 0; i < 4; ++i) accx[p][i] = 0.0f;

        #pragma unroll
        for (int kcb = 0; kcb < 16; kcb += 4) {
            const bool pf = (kcb + 4) < 16;
            #pragma unroll
            for (int u = 0; u < 4; ++u)
                if (pf) qn[u] = fb[(size_t)(kbase + kcb + 4 + u) * 256];
            #pragma unroll
            for (int u = 0; u < 4; ++u) {
                const int kc = kbase + kcb + u;
                const uint4 fh = *(const uint4*)(usm + SM_AHI + (kc * 33 + lane) * 4);
                const int s = u & 1;
                mma_f16(acch[s][0], fh.x, fh.y, fh.z, fh.w, q[u].x, q[u].y);
                mma_f16(acch[s][1], fh.x, fh.y, fh.z, fh.w, q[u].z, q[u].w);
            }
            #pragma unroll
            for (int u = 0; u < 4; ++u) q[u] = qn[u];
        }

        // x pass: warp w covers kc {2w, 2w+1}
        {
            const int kcA = 2 * w, kcB = 2 * w + 1;
            const uint4 fha = *(const uint4*)(usm + SM_AHI + (kcA * 33 + lane) * 4);
            mma_f16(accx[0], fha.x, fha.y, fha.z, fha.w, xq0.x, xq0.y);
            mma_f16(accx[1], fha.x, fha.y, fha.z, fha.w, xq0.z, xq0.w);
            const uint4 fhb = *(const uint4*)(usm + SM_AHI + (kcB * 33 + lane) * 4);
            mma_f16(accx[0], fhb.x, fhb.y, fhb.z, fhb.w, xq1.x, xq1.y);
            mma_f16(accx[1], fhb.x, fhb.y, fhb.z, fhb.w, xq1.z, xq1.w);
        }

        // store partials
        {
            float sh[4], sx[4];
            #pragma unroll
            for (int i = 0; i < 4; ++i) {
                sh[i] = (acch[0][0][i] + acch[0][1][i]) + (acch[1][0][i] + acch[1][1][i]);
                sx[i] = accx[0][i] + accx[1][i];
            }
            float* ahh = half ? ah1 : ah0;
            const int cb = 8 + 8 * wj;
            *(float2*)&ahh[g * 80 + cb + 2 * tig]       = make_float2(sh[0], sh[1]);
            *(float2*)&ahh[(g + 8) * 80 + cb + 2 * tig] = make_float2(sh[2], sh[3]);
            atomicAdd(&ahh[g * 80 + 2 * tig],           sx[0]);
            atomicAdd(&ahh[g * 80 + 2 * tig + 1],       sx[1]);
            atomicAdd(&ahh[(g + 8) * 80 + 2 * tig],     sx[2]);
            atomicAdd(&ahh[(g + 8) * 80 + 2 * tig + 1], sx[3]);
        }
        __syncthreads();   // sync1: ah complete; A-frag smem reads done

        // ---- stage next A tile into smem (all warps; overlapped with phase 2) ----
        if (t < Sn - 1) {
            #pragma unroll
            for (int r = 0; r < 4; ++r)
                stage_sts_one(usm, tid + r * TPB, av[r]);
        }

        // ================= Phase 2 (ALL 16 warps; warp chain halved) =================
        // warp (half, wj): ntiles {half*16 + wj, half*16 + 8 + wj}
        float acc2[2][2][4];
        #pragma unroll
        for (int h2 = 0; h2 < 2; ++h2)
            #pragma unroll
            for (int q2 = 0; q2 < 2; ++q2)
                #pragma unroll
                for (int i = 0; i < 4; ++i) acc2[h2][q2][i] = 0.0f;

        #pragma unroll
        for (int kk = 0; kk < 5; ++kk) {
            const int k0 = kk * 16;
            float2 p0a = *(const float2*)&ah0[g * 80 + k0 + 2 * tig];
            float2 p0b = *(const float2*)&ah1[g * 80 + k0 + 2 * tig];
            float2 p1a = *(const float2*)&ah0[(g + 8) * 80 + k0 + 2 * tig];
            float2 p1b = *(const float2*)&ah1[(g + 8) * 80 + k0 + 2 * tig];
            float2 p2a = *(const float2*)&ah0[g * 80 + k0 + 8 + 2 * tig];
            float2 p2b = *(const float2*)&ah1[g * 80 + k0 + 8 + 2 * tig];
            float2 p3a = *(const float2*)&ah0[(g + 8) * 80 + k0 + 8 + 2 * tig];
            float2 p3b = *(const float2*)&ah1[(g + 8) * 80 + k0 + 8 + 2 * tig];
            unsigned A0h, A0l, A1h, A1l, A2h, A2l, A3h, A3l;
            fsplit2(p0a.x + p0b.x, p0a.y + p0b.y, A0h, A0l);
            fsplit2(p1a.x + p1b.x, p1a.y + p1b.y, A1h, A1l);
            fsplit2(p2a.x + p2b.x, p2a.y + p2b.y, A2h, A2l);
            fsplit2(p3a.x + p3b.x, p3a.y + p3b.y, A3h, A3l);
            const int hsel = kk & 1;
            #pragma unroll
            for (int q2 = 0; q2 < 2; ++q2) {
                const int ntile = (half << 4) + (q2 << 3) + wj;
                uint4 qw = Wsm[(kk * 32 + ntile) * 32 + lane];
                mma_f16(acc2[hsel][q2], A0h, A1h, A2h, A3h, qw.x, qw.y);
                mma_f16(acc2[hsel][q2], A0h, A1h, A2h, A3h, qw.z, qw.w);
                mma_f16(acc2[hsel][q2], A0l, A1l, A2l, A3l, qw.x, qw.y);
            }
        }

        // segment 1 (warps 8-15): publish o/gg accumulators
        if (!gate_warp) {
            float4 eo, eg;
            eo.x = acc2[0][0][0] + acc2[1][0][0];
            eo.y = acc2[0][0][1] + acc2[1][0][1];
            eo.z = acc2[0][0][2] + acc2[1][0][2];
            eo.w = acc2[0][0][3] + acc2[1][0][3];
            eg.x = acc2[0][1][0] + acc2[1][1][0];
            eg.y = acc2[0][1][1] + acc2[1][1][1];
            eg.z = acc2[0][1][2] + acc2[1][1][2];
            eg.w = acc2[0][1][3] + acc2[1][1][3];
            *(float4*)&ex[(wj * 32 + lane) * EX_STRIDE]     = eo;
            *(float4*)&ex[(wj * 32 + lane) * EX_STRIDE + 4] = eg;
        }
        __syncthreads();   // sync2: EX visible; phase-2 ah reads done

        if (gate_warp) {
            // ================= Gates (warps 0-7) =================
            float4 eo = *(const float4*)&ex[(wj * 32 + lane) * EX_STRIDE];
            float4 eg = *(const float4*)&ex[(wj * 32 + lane) * EX_STRIDE + 4];
            float goa[4] = {eo.x, eo.y, eo.z, eo.w};
            float gga[4] = {eg.x, eg.y, eg.z, eg.w};
            #pragma unroll
            for (int j = 0; j < 4; ++j) {
                float gi = acc2[0][0][j] + acc2[1][0][j] + bgr[0][j & 1];
                float gf = acc2[0][1][j] + acc2[1][1][j] + bgr[1][j & 1];
                float go = goa[j] + bgr[2][j & 1];
                float gg = gga[j] + bgr[3][j & 1];
                float i_ = sigmoidf_fast(gi);
                float f_ = sigmoidf_fast(gf);
                float o_ = sigmoidf_fast(go);
                float G  = tanhf_fast(gg);
                float cn = f_ * creg[j] + i_ * G;
                creg[j] = cn;
                int row = g + 8 * (j >> 1);
                hs[row * 64 + colb + (j & 1)] = o_ * tanhf_fast(cn);
            }
            __syncwarp();

            // pack this warp's h column block into Ffrag
            {
                int g2 = lane >> 2, tg = lane & 3;
                int col = wj * 8 + g2;
                float v0 = hs[(2 * tg) * 64 + col];
                float v1 = hs[(2 * tg + 1) * 64 + col];
                float v2 = hs[(2 * tg + 8) * 64 + col];
                float v3 = hs[(2 * tg + 9) * 64 + col];
                unsigned b0h, b0l, b1h, b1l;
                fsplit2(v0, v1, b0h, b0l);
                fsplit2(v2, v3, b1h, b1l);
                d_Ffrag[(size_t)((par ^ 1) * Bn + b) * (KC * 8 * 32) + kcCTA * 256 + wj * 32 + lane] =
                    make_uint4(b0h, b1h, b0l, b1l);
            }
        } else {
            // warps 8-15: reset x regions of both half buffers (256 threads, 256 slots)
            int e = tid - 256;
            if (e < 128) ah0[(e >> 3) * 80 + (e & 7)] = 0.0f;
            else { int e2 = e - 128; ah1[(e2 >> 3) * 80 + (e2 & 7)] = 0.0f; }
        }

        b_barrier(b, kcCTA, (unsigned)(t + 1));   // sync3 + flags + sync4
    }

    // ================= Readout =================
    if (kcCTA == 0 && tid < Hn)
        d_hfinal[b * Hn + tid] = hs[tid];   // node 0 row
    g_barrier();
    if (kcCTA == 0 && b == 0) {
        float* hid = smem + SM_AH0;
        if (tid < Bn * (Hn / 2)) {
            int bb = tid / (Hn / 2);
            int u  = tid % (Hn / 2);
            float s = b1[u];
            #pragma unroll 8
            for (int k = 0; k < Hn; ++k)
                s += d_hfinal[bb * Hn + k] * W1[k * (Hn / 2) + u];
            hid[bb * (Hn / 2) + u] = fmaxf(s, 0.0f);
        }
        __syncthreads();
        if (tid < Bn * OUTn) {
            int bb = tid / OUTn;
            int o  = tid % OUTn;
            float s = b2[o];
            #pragma unroll
            for (int u = 0; u < Hn / 2; ++u)
                s += hid[bb * (Hn / 2) + u] * W2[u * OUTn + o];
            out[bb * OUTn + o] = s;
        }
    }
}

extern "C" void kernel_launch(void* const* d_in, const int* in_sizes, int n_in,
                              void* d_out, int out_size)
{
    const float* x   = (const float*)d_in[0];
    const float* adj = (const float*)d_in[1];
    const float* h0  = (const float*)d_in[2];
    const float* c0  = (const float*)d_in[3];
    const float* Wx  = (const float*)d_in[4];
    const float* Wh  = (const float*)d_in[5];
    const float* bg  = (const float*)d_in[6];
    const float* W1  = (const float*)d_in[7];
    const float* b1  = (const float*)d_in[8];
    const float* W2  = (const float*)d_in[9];
    const float* b2  = (const float*)d_in[10];
    float* out = (float*)d_out;

    cudaFuncSetAttribute(persistent_kernel,
                         cudaFuncAttributeMaxDynamicSharedMemorySize, SMEM_BYTES);

    init_kernel<<<(Sn * Bn * KC * 32 + 255) / 256, 256>>>(x, h0, Wx, Wh);

    dim3 grid(NTIL, Bn);   // 32 x 4 = 128 CTAs, single wave
    persistent_kernel<<<grid, TPB, SMEM_BYTES>>>(adj, c0, bg, W1, b1, W2, b2, out);
}

// round 15
// speedup vs baseline: 1.8053x; 1.8053x over previous
#include <cuda_runtime.h>
#include <cuda_fp16.h>
#include <cstdint>

// Problem constants
#define Bn   4
#define Sn   96
#define Nn   512
#define Dn   8
#define Hn   64
#define OUTn 24

#define ROWS 16
#define TPB  512             // 16 warps
#define NTIL 32              // Nn/ROWS (CTAs per batch)
#define GRID_CTAS 128
#define KC   32              // K chunks of 16 (Nn/16)

// smem layout (u32/float units)
#define SM_AHI 0             // 4224  : A-frag (fp16 hi only) [(kc*33+lane)*4 + i]
#define SM_W   4224          // 20480 : W fragments (5120 uint4)
#define SM_AH0 24704         // 1280  : ah partial (half 0 + x half 0)  (16 x 80)
#define SM_AH1 25984         // 1280  : ah partial (half 1 + x half 1)
#define SM_HS  27264         // 1024  : h_new scratch
#define SMEM_FLOATS 28288
#define SMEM_BYTES  (SMEM_FLOATS * 4)

// ---------------- persistent device state ----------------
__device__ uint4 d_Ffrag[2 * Bn * KC * 8 * 32];   // h frags (fp16 hi/lo), dbl-buffered
__device__ uint4 d_Xfrag[Sn * Bn * KC * 32];      // x frags (fp16 hi/lo), all steps
__device__ uint4 d_Wfrag4[5 * 32 * 32];           // W frags (fp16 hi/lo)
__device__ float  d_hfinal[Bn * Hn];
__device__ unsigned d_bcnt[Bn * 32];
__device__ unsigned d_bflag[Bn * 32];
__device__ unsigned d_gcnt;
__device__ unsigned d_gflag;

// ---------------- helpers ----------------
__device__ __forceinline__ unsigned fcvt2(float x, float y) {
    __half2 hb = __float22half2_rn(make_float2(x, y));
    return *reinterpret_cast<unsigned*>(&hb);
}
__device__ __forceinline__ void fsplit2(float x, float y, unsigned& h, unsigned& l) {
    __half2 hb = __float22half2_rn(make_float2(x, y));
    float2 hf = __half22float2(hb);
    __half2 lb = __float22half2_rn(make_float2(x - hf.x, y - hf.y));
    h = *reinterpret_cast<unsigned*>(&hb);
    l = *reinterpret_cast<unsigned*>(&lb);
}

__device__ __forceinline__ void mma_f16(float c[4],
                                        unsigned a0, unsigned a1, unsigned a2, unsigned a3,
                                        unsigned b0, unsigned b1) {
    asm volatile(
        "mma.sync.aligned.m16n8k16.row.col.f32.f16.f16.f32 "
        "{%0,%1,%2,%3}, {%4,%5,%6,%7}, {%8,%9}, {%0,%1,%2,%3};\n"
        : "+f"(c[0]), "+f"(c[1]), "+f"(c[2]), "+f"(c[3])
        : "r"(a0), "r"(a1), "r"(a2), "r"(a3), "r"(b0), "r"(b1));
}

__device__ __forceinline__ float sigmoidf_fast(float x) { return 1.0f / (1.0f + __expf(-x)); }
__device__ __forceinline__ float tanhf_fast(float x)    { return 1.0f - 2.0f / (__expf(2.0f * x) + 1.0f); }

__device__ __forceinline__ void b_barrier(int b, unsigned epoch) {
    if (threadIdx.x == 0) {
        __threadfence();
        unsigned old = atomicAdd(&d_bcnt[b * 32], 1u);
        if (old == epoch * NTIL - 1u) {
            asm volatile("st.release.gpu.u32 [%0], %1;" :: "l"(&d_bflag[b * 32]), "r"(epoch) : "memory");
        } else {
            unsigned v;
            do {
                __nanosleep(32);
                asm volatile("ld.acquire.gpu.u32 %0, [%1];" : "=r"(v) : "l"(&d_bflag[b * 32]) : "memory");
            } while (v < epoch);
        }
    }
    __syncthreads();
}

__device__ __forceinline__ void g_barrier() {
    __syncthreads();
    if (threadIdx.x == 0) {
        __threadfence();
        unsigned old = atomicAdd(&d_gcnt, 1u);
        if (old == GRID_CTAS - 1u) {
            asm volatile("st.release.gpu.u32 [%0], %1;" :: "l"(&d_gflag), "r"(1u) : "memory");
        } else {
            unsigned v;
            do {
                __nanosleep(32);
                asm volatile("ld.acquire.gpu.u32 %0, [%1];" : "=r"(v) : "l"(&d_gflag) : "memory");
            } while (v < 1u);
        }
    }
    __syncthreads();
}

// ---------------- init ----------------
__global__ void init_kernel(const float* __restrict__ x,
                            const float* __restrict__ h0,
                            const float* __restrict__ Wx,
                            const float* __restrict__ Wh) {
    int idx = blockIdx.x * blockDim.x + threadIdx.x;
    if (idx < Bn * 32) { d_bcnt[idx] = 0; d_bflag[idx] = 0; }
    if (idx == 0) { d_gcnt = 0; d_gflag = 0; }

    if (idx < 5 * 32 * 32) {
        int kk    = idx >> 10;
        int rem   = idx & 1023;
        int ntile = rem >> 5;
        int lane  = rem & 31;
        int g = lane >> 2, tig = lane & 3;
        int col = ntile * 8 + g;
        auto wval = [&](int kr) -> float {
            if (kr >= 72) return 0.0f;
            return (kr < Dn) ? Wx[kr * 256 + col] : Wh[(kr - Dn) * 256 + col];
        };
        int k0 = kk * 16 + 2 * tig;
        unsigned b0h, b0l, b1h, b1l;
        fsplit2(wval(k0),     wval(k0 + 1), b0h, b0l);
        fsplit2(wval(k0 + 8), wval(k0 + 9), b1h, b1l);
        d_Wfrag4[idx] = make_uint4(b0h, b1h, b0l, b1l);
    }

    if (idx < Bn * KC * 8 * 32) {
        int lane = idx & 31;
        int j    = (idx >> 5) & 7;
        int kc   = (idx >> 8) & 31;
        int b    = idx >> 13;
        int g = lane >> 2, tg = lane & 3;
        int col = j * 8 + g;
        const float* hb = h0 + (size_t)b * Nn * Hn;
        float v0 = hb[(kc * 16 + 2 * tg) * Hn + col];
        float v1 = hb[(kc * 16 + 2 * tg + 1) * Hn + col];
        float v2 = hb[(kc * 16 + 2 * tg + 8) * Hn + col];
        float v3 = hb[(kc * 16 + 2 * tg + 9) * Hn + col];
        unsigned b0h, b0l, b1h, b1l;
        fsplit2(v0, v1, b0h, b0l);
        fsplit2(v2, v3, b1h, b1l);
        d_Ffrag[((size_t)b * KC + kc) * 256 + j * 32 + lane] = make_uint4(b0h, b1h, b0l, b1l);
    }

    if (idx < Sn * Bn * KC * 32) {
        int lane = idx & 31;
        int kc   = (idx >> 5) & 31;
        int b    = (idx >> 10) & 3;
        int t    = idx >> 12;
        int g = lane >> 2, tg = lane & 3;
        const float* xs = x + ((size_t)b * Sn + t) * Nn * Dn;
        float v0 = xs[(kc * 16 + 2 * tg) * Dn + g];
        float v1 = xs[(kc * 16 + 2 * tg + 1) * Dn + g];
        float v2 = xs[(kc * 16 + 2 * tg + 8) * Dn + g];
        float v3 = xs[(kc * 16 + 2 * tg + 9) * Dn + g];
        unsigned b0h, b0l, b1h, b1l;
        fsplit2(v0, v1, b0h, b0l);
        fsplit2(v2, v3, b1h, b1l);
        d_Xfrag[(((size_t)t * Bn + b) * KC + kc) * 32 + lane] = make_uint4(b0h, b1h, b0l, b1l);
    }
}

// ---------------- A-tile staging helper (fp16 hi only) ----------------
__device__ __forceinline__ void stage_sts_one(unsigned* __restrict__ usm, int idx, float4 v) {
    int n  = idx >> 7;
    int mq = idx & 127;
    int kc = mq >> 2;
    int k  = (mq & 3) * 4;
    int i  = ((n >> 3) & 1) + 2 * ((k >> 3) & 1);
    int l  = ((n & 7) << 2) | ((k >> 1) & 3);
    usm[SM_AHI + (kc * 33 + l)     * 4 + i] = fcvt2(v.x, v.y);
    usm[SM_AHI + (kc * 33 + l + 1) * 4 + i] = fcvt2(v.z, v.w);
}

// ---------------- the persistent kernel ----------------
__global__ void __launch_bounds__(TPB, 1) persistent_kernel(
    const float* __restrict__ adj,
    const float* __restrict__ c0,
    const float* __restrict__ b_gates,
    const float* __restrict__ W1, const float* __restrict__ b1,
    const float* __restrict__ W2, const float* __restrict__ b2,
    float* __restrict__ out)
{
    extern __shared__ float smem[];
    unsigned* usm = reinterpret_cast<unsigned*>(smem);
    float* ah0 = smem + SM_AH0;
    float* ah1 = smem + SM_AH1;
    float* hs  = smem + SM_HS;
    uint4* Wsm = reinterpret_cast<uint4*>(smem + SM_W);

    const int b     = blockIdx.y;
    const int kcCTA = blockIdx.x;
    const int n0    = kcCTA * ROWS;
    const int tid   = threadIdx.x;
    const int lane  = tid & 31;
    const int w     = tid >> 5;           // 0..15
    const int wj    = w & 7;              // phase-1 j tile
    const int half  = w >> 3;             // phase-1 K half
    const int g     = lane >> 2;
    const int tig   = lane & 3;
    const int colb  = 8 * wj + 2 * tig;
    const bool gate_warp = (w < 8);
    const int st    = tid & 255;          // staging thread id (warps 8..15)

    // ---- prologue ----
    for (int i = tid; i < 5 * 32 * 32; i += TPB) Wsm[i] = d_Wfrag4[i];
    for (int e = tid; e < 2 * 1280; e += TPB) (smem + SM_AH0)[e] = 0.0f;

    float creg[4] = {0.f, 0.f, 0.f, 0.f};
    float bgr[4][2];
    if (gate_warp) {
        creg[0] = c0[((size_t)b * Nn + n0 + g) * Hn + colb];
        creg[1] = c0[((size_t)b * Nn + n0 + g) * Hn + colb + 1];
        creg[2] = c0[((size_t)b * Nn + n0 + 8 + g) * Hn + colb];
        creg[3] = c0[((size_t)b * Nn + n0 + 8 + g) * Hn + colb + 1];
        #pragma unroll
        for (int q = 0; q < 4; ++q) {
            bgr[q][0] = b_gates[q * 64 + colb];
            bgr[q][1] = b_gates[q * 64 + colb + 1];
        }
    }

    // stage A for t = 0 (all threads)
    {
        const float* Abase = adj + (((size_t)b * Sn + 0) * Nn + n0) * Nn;
        #pragma unroll
        for (int r = 0; r < 4; ++r) {
            int idx = tid + r * TPB;
            int n = idx >> 7, mq = idx & 127;
            float4 v = *(const float4*)(Abase + (size_t)n * Nn + (size_t)mq * 4);
            stage_sts_one(usm, idx, v);
        }
    }
    __syncthreads();

    for (int t = 0; t < Sn; ++t) {
        const int par = t & 1;
        const float* Anext = adj + (((size_t)b * Sn + (t + 1)) * Nn + n0) * Nn;

        // staging warps: issue round-1 LDGs for t+1 (in flight through phase 1)
        float4 av1[4];
        if (!gate_warp && t < Sn - 1) {
            #pragma unroll
            for (int r = 0; r < 4; ++r) {
                int idx = st + r * 256;
                int n = idx >> 7, mq = idx & 127;
                av1[r] = *(const float4*)(Anext + (size_t)n * Nn + (size_t)mq * 4);
            }
        }

        // ================= Phase 1 (fp16, 2-pass: Ah*Bh + Ah*Bl) =================
        const uint4* xb = d_Xfrag + (size_t)(t * Bn + b) * (KC * 32) + lane;
        uint4 xq0 = xb[(size_t)(2 * w) * 32];
        uint4 xq1 = xb[(size_t)(2 * w + 1) * 32];

        float acch[2][2][4], accx[2][4];
        #pragma unroll
        for (int s = 0; s < 2; ++s)
            #pragma unroll
            for (int p = 0; p < 2; ++p)
                #pragma unroll
                for (int i = 0; i < 4; ++i) acch[s][p][i] = 0.0f;
        #pragma unroll
        for (int p = 0; p < 2; ++p)
            #pragma unroll
            for (int i = 0; i < 4; ++i) accx[p][i] = 0.0f;

        const uint4* fb = d_Ffrag + (size_t)(par * Bn + b) * (KC * 8 * 32) + wj * 32 + lane;
        const int kbase = half * 16;
        uint4 q[4], qn[4];
        #pragma unroll
        for (int u = 0; u < 4; ++u) q[u] = fb[(size_t)(kbase + u) * 256];

        #pragma unroll
        for (int kcb = 0; kcb < 16; kcb += 4) {
            const bool pf = (kcb + 4) < 16;
            #pragma unroll
            for (int u = 0; u < 4; ++u)
                if (pf) qn[u] = fb[(size_t)(kbase + kcb + 4 + u) * 256];
            #pragma unroll
            for (int u = 0; u < 4; ++u) {
                const int kc = kbase + kcb + u;
                const uint4 fh = *(const uint4*)(usm + SM_AHI + (kc * 33 + lane) * 4);
                const int s = u & 1;
                mma_f16(acch[s][0], fh.x, fh.y, fh.z, fh.w, q[u].x, q[u].y);
                mma_f16(acch[s][1], fh.x, fh.y, fh.z, fh.w, q[u].z, q[u].w);
            }
            #pragma unroll
            for (int u = 0; u < 4; ++u) q[u] = qn[u];
        }

        // x pass: warp w covers kc {2w, 2w+1}
        {
            const int kcA = 2 * w, kcB = 2 * w + 1;
            const uint4 fha = *(const uint4*)(usm + SM_AHI + (kcA * 33 + lane) * 4);
            mma_f16(accx[0], fha.x, fha.y, fha.z, fha.w, xq0.x, xq0.y);
            mma_f16(accx[1], fha.x, fha.y, fha.z, fha.w, xq0.z, xq0.w);
            const uint4 fhb = *(const uint4*)(usm + SM_AHI + (kcB * 33 + lane) * 4);
            mma_f16(accx[0], fhb.x, fhb.y, fhb.z, fhb.w, xq1.x, xq1.y);
            mma_f16(accx[1], fhb.x, fhb.y, fhb.z, fhb.w, xq1.z, xq1.w);
        }

        // store partials: h partial to own half buffer; x atomics split by half
        {
            float sh[4], sx[4];
            #pragma unroll
            for (int i = 0; i < 4; ++i) {
                sh[i] = (acch[0][0][i] + acch[0][1][i]) + (acch[1][0][i] + acch[1][1][i]);
                sx[i] = accx[0][i] + accx[1][i];
            }
            float* ahh = half ? ah1 : ah0;
            const int cb = 8 + 8 * wj;
            *(float2*)&ahh[g * 80 + cb + 2 * tig]       = make_float2(sh[0], sh[1]);
            *(float2*)&ahh[(g + 8) * 80 + cb + 2 * tig] = make_float2(sh[2], sh[3]);
            atomicAdd(&ahh[g * 80 + 2 * tig],           sx[0]);
            atomicAdd(&ahh[g * 80 + 2 * tig + 1],       sx[1]);
            atomicAdd(&ahh[(g + 8) * 80 + 2 * tig],     sx[2]);
            atomicAdd(&ahh[(g + 8) * 80 + 2 * tig + 1], sx[3]);
        }
        __syncthreads();

        if (gate_warp) {
            // ======= Phase 2 (warps 0-7): ah0+ah1, fp16 2-pass (AhWh + AlWh) =======
            float acc2[2][4][4];
            #pragma unroll
            for (int h2 = 0; h2 < 2; ++h2)
                #pragma unroll
                for (int qg = 0; qg < 4; ++qg)
                    #pragma unroll
                    for (int i = 0; i < 4; ++i) acc2[h2][qg][i] = 0.0f;

            #pragma unroll
            for (int kk = 0; kk < 5; ++kk) {
                const int k0 = kk * 16;
                float2 p0a = *(const float2*)&ah0[g * 80 + k0 + 2 * tig];
                float2 p0b = *(const float2*)&ah1[g * 80 + k0 + 2 * tig];
                float2 p1a = *(const float2*)&ah0[(g + 8) * 80 + k0 + 2 * tig];
                float2 p1b = *(const float2*)&ah1[(g + 8) * 80 + k0 + 2 * tig];
                float2 p2a = *(const float2*)&ah0[g * 80 + k0 + 8 + 2 * tig];
                float2 p2b = *(const float2*)&ah1[g * 80 + k0 + 8 + 2 * tig];
                float2 p3a = *(const float2*)&ah0[(g + 8) * 80 + k0 + 8 + 2 * tig];
                float2 p3b = *(const float2*)&ah1[(g + 8) * 80 + k0 + 8 + 2 * tig];
                unsigned A0h, A0l, A1h, A1l, A2h, A2l, A3h, A3l;
                fsplit2(p0a.x + p0b.x, p0a.y + p0b.y, A0h, A0l);
                fsplit2(p1a.x + p1b.x, p1a.y + p1b.y, A1h, A1l);
                fsplit2(p2a.x + p2b.x, p2a.y + p2b.y, A2h, A2l);
                fsplit2(p3a.x + p3b.x, p3a.y + p3b.y, A3h, A3l);
                const int hsel = kk & 1;
                #pragma unroll
                for (int qg = 0; qg < 4; ++qg) {
                    uint4 qw = Wsm[(kk * 32 + qg * 8 + w) * 32 + lane];
                    mma_f16(acc2[hsel][qg], A0h, A1h, A2h, A3h, qw.x, qw.y);
                    mma_f16(acc2[hsel][qg], A0l, A1l, A2l, A3l, qw.x, qw.y);
                }
            }

            // gates in registers -> hs (warp-local 16x8 column block)
            #pragma unroll
            for (int j = 0; j < 4; ++j) {
                float gi = acc2[0][0][j] + acc2[1][0][j] + bgr[0][j & 1];
                float gf = acc2[0][1][j] + acc2[1][1][j] + bgr[1][j & 1];
                float go = acc2[0][2][j] + acc2[1][2][j] + bgr[2][j & 1];
                float gg = acc2[0][3][j] + acc2[1][3][j] + bgr[3][j & 1];
                float i_ = sigmoidf_fast(gi);
                float f_ = sigmoidf_fast(gf);
                float o_ = sigmoidf_fast(go);
                float G  = tanhf_fast(gg);
                float cn = f_ * creg[j] + i_ * G;
                creg[j] = cn;
                int row = g + 8 * (j >> 1);
                hs[row * 64 + colb + (j & 1)] = o_ * tanhf_fast(cn);
            }
            __syncwarp();

            // pack this warp's h column block into Ffrag
            {
                int g2 = lane >> 2, tg = lane & 3;
                int col = wj * 8 + g2;
                float v0 = hs[(2 * tg) * 64 + col];
                float v1 = hs[(2 * tg + 1) * 64 + col];
                float v2 = hs[(2 * tg + 8) * 64 + col];
                float v3 = hs[(2 * tg + 9) * 64 + col];
                unsigned b0h, b0l, b1h, b1l;
                fsplit2(v0, v1, b0h, b0l);
                fsplit2(v2, v3, b1h, b1l);
                d_Ffrag[(size_t)((par ^ 1) * Bn + b) * (KC * 8 * 32) + kcCTA * 256 + wj * 32 + lane] =
                    make_uint4(b0h, b1h, b0l, b1l);
            }
        } else if (t < Sn - 1) {
            // ================= A staging (warps 8-15), overlapped =================
            #pragma unroll
            for (int r = 0; r < 4; ++r)
                stage_sts_one(usm, st + r * 256, av1[r]);
            float4 av2[4];
            #pragma unroll
            for (int r = 0; r < 4; ++r) {
                int idx = st + (r + 4) * 256;
                int n = idx >> 7, mq = idx & 127;
                av2[r] = *(const float4*)(Anext + (size_t)n * Nn + (size_t)mq * 4);
            }
            #pragma unroll
            for (int r = 0; r < 4; ++r)
                stage_sts_one(usm, st + (r + 4) * 256, av2[r]);
        }
        __syncthreads();

        if (t == Sn - 1 && kcCTA == 0 && tid < Hn)
            d_hfinal[b * Hn + tid] = hs[tid];   // row 0 (node 0)

        // reset x regions of both half buffers
        if (tid < 128)      ah0[(tid >> 3) * 80 + (tid & 7)] = 0.0f;
        else if (tid < 256) { int e = tid - 128; ah1[(e >> 3) * 80 + (e & 7)] = 0.0f; }

        b_barrier(b, (unsigned)(t + 1));
    }

    // ================= Readout =================
    g_barrier();
    if (kcCTA == 0 && b == 0) {
        float* hid = smem + SM_AH0;
        if (tid < Bn * (Hn / 2)) {
            int bb = tid / (Hn / 2);
            int u  = tid % (Hn / 2);
            float s = b1[u];
            #pragma unroll 8
            for (int k = 0; k < Hn; ++k)
                s += d_hfinal[bb * Hn + k] * W1[k * (Hn / 2) + u];
            hid[bb * (Hn / 2) + u] = fmaxf(s, 0.0f);
        }
        __syncthreads();
        if (tid < Bn * OUTn) {
            int bb = tid / OUTn;
            int o  = tid % OUTn;
            float s = b2[o];
            #pragma unroll
            for (int u = 0; u < Hn / 2; ++u)
                s += hid[bb * (Hn / 2) + u] * W2[u * OUTn + o];
            out[bb * OUTn + o] = s;
        }
    }
}

extern "C" void kernel_launch(void* const* d_in, const int* in_sizes, int n_in,
                              void* d_out, int out_size)
{
    const float* x   = (const float*)d_in[0];
    const float* adj = (const float*)d_in[1];
    const float* h0  = (const float*)d_in[2];
    const float* c0  = (const float*)d_in[3];
    const float* Wx  = (const float*)d_in[4];
    const float* Wh  = (const float*)d_in[5];
    const float* bg  = (const float*)d_in[6];
    const float* W1  = (const float*)d_in[7];
    const float* b1  = (const float*)d_in[8];
    const float* W2  = (const float*)d_in[9];
    const float* b2  = (const float*)d_in[10];
    float* out = (float*)d_out;

    cudaFuncSetAttribute(persistent_kernel,
                         cudaFuncAttributeMaxDynamicSharedMemorySize, SMEM_BYTES);

    init_kernel<<<(Sn * Bn * KC * 32 + 255) / 256, 256>>>(x, h0, Wx, Wh);

    dim3 grid(NTIL, Bn);   // 32 x 4 = 128 CTAs, single wave
    persistent_kernel<<<grid, TPB, SMEM_BYTES>>>(adj, c0, bg, W1, b1, W2, b2, out);
}

// round 16
// speedup vs baseline: 1.8914x; 1.0477x over previous
#include <cuda_runtime.h>
#include <cuda_fp16.h>
#include <cstdint>

// Problem constants
#define Bn   4
#define Sn   96
#define Nn   512
#define Dn   8
#define Hn   64
#define OUTn 24

#define ROWS 16
#define TPB  512             // 16 warps
#define NTIL 32              // Nn/ROWS (CTAs per batch)
#define GRID_CTAS 128
#define KC   32              // K chunks of 16 (Nn/16)

// smem layout (u32/float units)
#define SM_AHI 0             // 4224  : A-frag (fp16 hi only) [(kc*33+lane)*4 + i]
#define SM_W   4224          // 20480 : W fragments (5120 uint4)
#define SM_AH0 24704         // 1280  : ah partial (half 0 + x half 0)  (16 x 80)
#define SM_AH1 25984         // 1280  : ah partial (half 1 + x half 1)
#define SM_HS  27264         // 1024  : h_new scratch
#define SMEM_FLOATS 28288
#define SMEM_BYTES  (SMEM_FLOATS * 4)

// ---------------- persistent device state ----------------
__device__ uint2 d_Ffrag[2 * Bn * KC * 8 * 32];   // h frags (fp16 HI only), dbl-buffered
__device__ uint4 d_Xfrag[Sn * Bn * KC * 32];      // x frags (fp16 hi/lo), all steps
__device__ uint4 d_Wfrag4[5 * 32 * 32];           // W frags (fp16 hi/lo)
__device__ float  d_hfinal[Bn * Hn];
__device__ unsigned d_bcnt[Bn * 32];
__device__ unsigned d_bflag[Bn * 32];
__device__ unsigned d_gcnt;
__device__ unsigned d_gflag;

// ---------------- helpers ----------------
__device__ __forceinline__ unsigned fcvt2(float x, float y) {
    __half2 hb = __float22half2_rn(make_float2(x, y));
    return *reinterpret_cast<unsigned*>(&hb);
}
__device__ __forceinline__ void fsplit2(float x, float y, unsigned& h, unsigned& l) {
    __half2 hb = __float22half2_rn(make_float2(x, y));
    float2 hf = __half22float2(hb);
    __half2 lb = __float22half2_rn(make_float2(x - hf.x, y - hf.y));
    h = *reinterpret_cast<unsigned*>(&hb);
    l = *reinterpret_cast<unsigned*>(&lb);
}

__device__ __forceinline__ void mma_f16(float c[4],
                                        unsigned a0, unsigned a1, unsigned a2, unsigned a3,
                                        unsigned b0, unsigned b1) {
    asm volatile(
        "mma.sync.aligned.m16n8k16.row.col.f32.f16.f16.f32 "
        "{%0,%1,%2,%3}, {%4,%5,%6,%7}, {%8,%9}, {%0,%1,%2,%3};\n"
        : "+f"(c[0]), "+f"(c[1]), "+f"(c[2]), "+f"(c[3])
        : "r"(a0), "r"(a1), "r"(a2), "r"(a3), "r"(b0), "r"(b1));
}

__device__ __forceinline__ float sigmoidf_fast(float x) { return 1.0f / (1.0f + __expf(-x)); }
__device__ __forceinline__ float tanhf_fast(float x)    { return 1.0f - 2.0f / (__expf(2.0f * x) + 1.0f); }

__device__ __forceinline__ void b_barrier(int b, unsigned epoch) {
    if (threadIdx.x == 0) {
        __threadfence();
        unsigned old = atomicAdd(&d_bcnt[b * 32], 1u);
        if (old == epoch * NTIL - 1u) {
            asm volatile("st.release.gpu.u32 [%0], %1;" :: "l"(&d_bflag[b * 32]), "r"(epoch) : "memory");
        } else {
            unsigned v;
            do {
                __nanosleep(32);
                asm volatile("ld.acquire.gpu.u32 %0, [%1];" : "=r"(v) : "l"(&d_bflag[b * 32]) : "memory");
            } while (v < epoch);
        }
    }
    __syncthreads();
}

__device__ __forceinline__ void g_barrier() {
    __syncthreads();
    if (threadIdx.x == 0) {
        __threadfence();
        unsigned old = atomicAdd(&d_gcnt, 1u);
        if (old == GRID_CTAS - 1u) {
            asm volatile("st.release.gpu.u32 [%0], %1;" :: "l"(&d_gflag), "r"(1u) : "memory");
        } else {
            unsigned v;
            do {
                __nanosleep(32);
                asm volatile("ld.acquire.gpu.u32 %0, [%1];" : "=r"(v) : "l"(&d_gflag) : "memory");
            } while (v < 1u);
        }
    }
    __syncthreads();
}

// ---------------- init ----------------
__global__ void init_kernel(const float* __restrict__ x,
                            const float* __restrict__ h0,
                            const float* __restrict__ Wx,
                            const float* __restrict__ Wh) {
    int idx = blockIdx.x * blockDim.x + threadIdx.x;
    if (idx < Bn * 32) { d_bcnt[idx] = 0; d_bflag[idx] = 0; }
    if (idx == 0) { d_gcnt = 0; d_gflag = 0; }

    if (idx < 5 * 32 * 32) {
        int kk    = idx >> 10;
        int rem   = idx & 1023;
        int ntile = rem >> 5;
        int lane  = rem & 31;
        int g = lane >> 2, tig = lane & 3;
        int col = ntile * 8 + g;
        auto wval = [&](int kr) -> float {
            if (kr >= 72) return 0.0f;
            return (kr < Dn) ? Wx[kr * 256 + col] : Wh[(kr - Dn) * 256 + col];
        };
        int k0 = kk * 16 + 2 * tig;
        unsigned b0h, b0l, b1h, b1l;
        fsplit2(wval(k0),     wval(k0 + 1), b0h, b0l);
        fsplit2(wval(k0 + 8), wval(k0 + 9), b1h, b1l);
        d_Wfrag4[idx] = make_uint4(b0h, b1h, b0l, b1l);
    }

    if (idx < Bn * KC * 8 * 32) {
        int lane = idx & 31;
        int j    = (idx >> 5) & 7;
        int kc   = (idx >> 8) & 31;
        int b    = idx >> 13;
        int g = lane >> 2, tg = lane & 3;
        int col = j * 8 + g;
        const float* hb = h0 + (size_t)b * Nn * Hn;
        float v0 = hb[(kc * 16 + 2 * tg) * Hn + col];
        float v1 = hb[(kc * 16 + 2 * tg + 1) * Hn + col];
        float v2 = hb[(kc * 16 + 2 * tg + 8) * Hn + col];
        float v3 = hb[(kc * 16 + 2 * tg + 9) * Hn + col];
        d_Ffrag[((size_t)b * KC + kc) * 256 + j * 32 + lane] =
            make_uint2(fcvt2(v0, v1), fcvt2(v2, v3));
    }

    if (idx < Sn * Bn * KC * 32) {
        int lane = idx & 31;
        int kc   = (idx >> 5) & 31;
        int b    = (idx >> 10) & 3;
        int t    = idx >> 12;
        int g = lane >> 2, tg = lane & 3;
        const float* xs = x + ((size_t)b * Sn + t) * Nn * Dn;
        float v0 = xs[(kc * 16 + 2 * tg) * Dn + g];
        float v1 = xs[(kc * 16 + 2 * tg + 1) * Dn + g];
        float v2 = xs[(kc * 16 + 2 * tg + 8) * Dn + g];
        float v3 = xs[(kc * 16 + 2 * tg + 9) * Dn + g];
        unsigned b0h, b0l, b1h, b1l;
        fsplit2(v0, v1, b0h, b0l);
        fsplit2(v2, v3, b1h, b1l);
        d_Xfrag[(((size_t)t * Bn + b) * KC + kc) * 32 + lane] = make_uint4(b0h, b1h, b0l, b1l);
    }
}

// ---------------- A-tile staging helper (fp16 hi only) ----------------
__device__ __forceinline__ void stage_sts_one(unsigned* __restrict__ usm, int idx, float4 v) {
    int n  = idx >> 7;
    int mq = idx & 127;
    int kc = mq >> 2;
    int k  = (mq & 3) * 4;
    int i  = ((n >> 3) & 1) + 2 * ((k >> 3) & 1);
    int l  = ((n & 7) << 2) | ((k >> 1) & 3);
    usm[SM_AHI + (kc * 33 + l)     * 4 + i] = fcvt2(v.x, v.y);
    usm[SM_AHI + (kc * 33 + l + 1) * 4 + i] = fcvt2(v.z, v.w);
}

// ---------------- the persistent kernel ----------------
__global__ void __launch_bounds__(TPB, 1) persistent_kernel(
    const float* __restrict__ adj,
    const float* __restrict__ c0,
    const float* __restrict__ b_gates,
    const float* __restrict__ W1, const float* __restrict__ b1,
    const float* __restrict__ W2, const float* __restrict__ b2,
    float* __restrict__ out)
{
    extern __shared__ float smem[];
    unsigned* usm = reinterpret_cast<unsigned*>(smem);
    float* ah0 = smem + SM_AH0;
    float* ah1 = smem + SM_AH1;
    float* hs  = smem + SM_HS;
    uint4* Wsm = reinterpret_cast<uint4*>(smem + SM_W);

    const int b     = blockIdx.y;
    const int kcCTA = blockIdx.x;
    const int n0    = kcCTA * ROWS;
    const int tid   = threadIdx.x;
    const int lane  = tid & 31;
    const int w     = tid >> 5;           // 0..15
    const int wj    = w & 7;              // phase-1 j tile
    const int half  = w >> 3;             // phase-1 K half
    const int g     = lane >> 2;
    const int tig   = lane & 3;
    const int colb  = 8 * wj + 2 * tig;
    const bool gate_warp = (w < 8);
    const int st    = tid & 255;          // staging thread id (warps 8..15)

    // ---- prologue ----
    for (int i = tid; i < 5 * 32 * 32; i += TPB) Wsm[i] = d_Wfrag4[i];
    for (int e = tid; e < 2 * 1280; e += TPB) (smem + SM_AH0)[e] = 0.0f;

    float creg[4] = {0.f, 0.f, 0.f, 0.f};
    float bgr[4][2];
    if (gate_warp) {
        creg[0] = c0[((size_t)b * Nn + n0 + g) * Hn + colb];
        creg[1] = c0[((size_t)b * Nn + n0 + g) * Hn + colb + 1];
        creg[2] = c0[((size_t)b * Nn + n0 + 8 + g) * Hn + colb];
        creg[3] = c0[((size_t)b * Nn + n0 + 8 + g) * Hn + colb + 1];
        #pragma unroll
        for (int q = 0; q < 4; ++q) {
            bgr[q][0] = b_gates[q * 64 + colb];
            bgr[q][1] = b_gates[q * 64 + colb + 1];
        }
    }

    // stage A for t = 0 (all threads)
    {
        const float* Abase = adj + (((size_t)b * Sn + 0) * Nn + n0) * Nn;
        #pragma unroll
        for (int r = 0; r < 4; ++r) {
            int idx = tid + r * TPB;
            int n = idx >> 7, mq = idx & 127;
            float4 v = *(const float4*)(Abase + (size_t)n * Nn + (size_t)mq * 4);
            stage_sts_one(usm, idx, v);
        }
    }
    __syncthreads();

    for (int t = 0; t < Sn; ++t) {
        const int par = t & 1;
        const float* Anext = adj + (((size_t)b * Sn + (t + 1)) * Nn + n0) * Nn;

        // ======= issue ALL 16 Ffrag loads upfront (single L2-latency exposure) =======
        const uint2* fb = d_Ffrag + (size_t)(par * Bn + b) * (KC * 8 * 32) + wj * 32 + lane;
        const int kbase = half * 16;
        uint2 qa[16];
        #pragma unroll
        for (int u = 0; u < 16; ++u) qa[u] = fb[(size_t)(kbase + u) * 256];

        // staging warps: issue round-1 LDGs for t+1 (in flight through phase 1)
        float4 av1[4];
        if (!gate_warp && t < Sn - 1) {
            #pragma unroll
            for (int r = 0; r < 4; ++r) {
                int idx = st + r * 256;
                int n = idx >> 7, mq = idx & 127;
                av1[r] = *(const float4*)(Anext + (size_t)n * Nn + (size_t)mq * 4);
            }
        }

        // ================= Phase 1 (fp16; h = hi-only, 1 MMA per kc) =================
        const uint4* xb = d_Xfrag + (size_t)(t * Bn + b) * (KC * 32) + lane;
        uint4 xq0 = xb[(size_t)(2 * w) * 32];
        uint4 xq1 = xb[(size_t)(2 * w + 1) * 32];

        float acch[4][4], accx[2][4];
        #pragma unroll
        for (int p = 0; p < 4; ++p)
            #pragma unroll
            for (int i = 0; i < 4; ++i) acch[p][i] = 0.0f;
        #pragma unroll
        for (int p = 0; p < 2; ++p)
            #pragma unroll
            for (int i = 0; i < 4; ++i) accx[p][i] = 0.0f;

        #pragma unroll
        for (int u = 0; u < 16; ++u) {
            const int kc = kbase + u;
            const uint4 fh = *(const uint4*)(usm + SM_AHI + (kc * 33 + lane) * 4);
            mma_f16(acch[u & 3], fh.x, fh.y, fh.z, fh.w, qa[u].x, qa[u].y);
        }

        // x pass: warp w covers kc {2w, 2w+1} (hi+lo compensated)
        {
            const int kcA = 2 * w, kcB = 2 * w + 1;
            const uint4 fha = *(const uint4*)(usm + SM_AHI + (kcA * 33 + lane) * 4);
            mma_f16(accx[0], fha.x, fha.y, fha.z, fha.w, xq0.x, xq0.y);
            mma_f16(accx[1], fha.x, fha.y, fha.z, fha.w, xq0.z, xq0.w);
            const uint4 fhb = *(const uint4*)(usm + SM_AHI + (kcB * 33 + lane) * 4);
            mma_f16(accx[0], fhb.x, fhb.y, fhb.z, fhb.w, xq1.x, xq1.y);
            mma_f16(accx[1], fhb.x, fhb.y, fhb.z, fhb.w, xq1.z, xq1.w);
        }

        // store partials: h partial to own half buffer; x atomics split by half
        {
            float sh[4], sx[4];
            #pragma unroll
            for (int i = 0; i < 4; ++i) {
                sh[i] = (acch[0][i] + acch[1][i]) + (acch[2][i] + acch[3][i]);
                sx[i] = accx[0][i] + accx[1][i];
            }
            float* ahh = half ? ah1 : ah0;
            const int cb = 8 + 8 * wj;
            *(float2*)&ahh[g * 80 + cb + 2 * tig]       = make_float2(sh[0], sh[1]);
            *(float2*)&ahh[(g + 8) * 80 + cb + 2 * tig] = make_float2(sh[2], sh[3]);
            atomicAdd(&ahh[g * 80 + 2 * tig],           sx[0]);
            atomicAdd(&ahh[g * 80 + 2 * tig + 1],       sx[1]);
            atomicAdd(&ahh[(g + 8) * 80 + 2 * tig],     sx[2]);
            atomicAdd(&ahh[(g + 8) * 80 + 2 * tig + 1], sx[3]);
        }
        __syncthreads();

        if (gate_warp) {
            // ======= Phase 2 (warps 0-7): ah0+ah1, fp16 2-pass (AhWh + AlWh) =======
            float acc2[2][4][4];
            #pragma unroll
            for (int h2 = 0; h2 < 2; ++h2)
                #pragma unroll
                for (int qg = 0; qg < 4; ++qg)
                    #pragma unroll
                    for (int i = 0; i < 4; ++i) acc2[h2][qg][i] = 0.0f;

            #pragma unroll
            for (int kk = 0; kk < 5; ++kk) {
                const int k0 = kk * 16;
                float2 p0a = *(const float2*)&ah0[g * 80 + k0 + 2 * tig];
                float2 p0b = *(const float2*)&ah1[g * 80 + k0 + 2 * tig];
                float2 p1a = *(const float2*)&ah0[(g + 8) * 80 + k0 + 2 * tig];
                float2 p1b = *(const float2*)&ah1[(g + 8) * 80 + k0 + 2 * tig];
                float2 p2a = *(const float2*)&ah0[g * 80 + k0 + 8 + 2 * tig];
                float2 p2b = *(const float2*)&ah1[g * 80 + k0 + 8 + 2 * tig];
                float2 p3a = *(const float2*)&ah0[(g + 8) * 80 + k0 + 8 + 2 * tig];
                float2 p3b = *(const float2*)&ah1[(g + 8) * 80 + k0 + 8 + 2 * tig];
                unsigned A0h, A0l, A1h, A1l, A2h, A2l, A3h, A3l;
                fsplit2(p0a.x + p0b.x, p0a.y + p0b.y, A0h, A0l);
                fsplit2(p1a.x + p1b.x, p1a.y + p1b.y, A1h, A1l);
                fsplit2(p2a.x + p2b.x, p2a.y + p2b.y, A2h, A2l);
                fsplit2(p3a.x + p3b.x, p3a.y + p3b.y, A3h, A3l);
                const int hsel = kk & 1;
                #pragma unroll
                for (int qg = 0; qg < 4; ++qg) {
                    uint4 qw = Wsm[(kk * 32 + qg * 8 + w) * 32 + lane];
                    mma_f16(acc2[hsel][qg], A0h, A1h, A2h, A3h, qw.x, qw.y);
                    mma_f16(acc2[hsel][qg], A0l, A1l, A2l, A3l, qw.x, qw.y);
                }
            }

            // gates in registers -> hs (warp-local 16x8 column block)
            #pragma unroll
            for (int j = 0; j < 4; ++j) {
                float gi = acc2[0][0][j] + acc2[1][0][j] + bgr[0][j & 1];
                float gf = acc2[0][1][j] + acc2[1][1][j] + bgr[1][j & 1];
                float go = acc2[0][2][j] + acc2[1][2][j] + bgr[2][j & 1];
                float gg = acc2[0][3][j] + acc2[1][3][j] + bgr[3][j & 1];
                float i_ = sigmoidf_fast(gi);
                float f_ = sigmoidf_fast(gf);
                float o_ = sigmoidf_fast(go);
                float G  = tanhf_fast(gg);
                float cn = f_ * creg[j] + i_ * G;
                creg[j] = cn;
                int row = g + 8 * (j >> 1);
                hs[row * 64 + colb + (j & 1)] = o_ * tanhf_fast(cn);
            }
            __syncwarp();

            // pack this warp's h column block into Ffrag (fp16 hi only)
            {
                int g2 = lane >> 2, tg = lane & 3;
                int col = wj * 8 + g2;
                float v0 = hs[(2 * tg) * 64 + col];
                float v1 = hs[(2 * tg + 1) * 64 + col];
                float v2 = hs[(2 * tg + 8) * 64 + col];
                float v3 = hs[(2 * tg + 9) * 64 + col];
                d_Ffrag[(size_t)((par ^ 1) * Bn + b) * (KC * 8 * 32) + kcCTA * 256 + wj * 32 + lane] =
                    make_uint2(fcvt2(v0, v1), fcvt2(v2, v3));
            }
        } else if (t < Sn - 1) {
            // ================= A staging (warps 8-15), overlapped =================
            #pragma unroll
            for (int r = 0; r < 4; ++r)
                stage_sts_one(usm, st + r * 256, av1[r]);
            float4 av2[4];
            #pragma unroll
            for (int r = 0; r < 4; ++r) {
                int idx = st + (r + 4) * 256;
                int n = idx >> 7, mq = idx & 127;
                av2[r] = *(const float4*)(Anext + (size_t)n * Nn + (size_t)mq * 4);
            }
            #pragma unroll
            for (int r = 0; r < 4; ++r)
                stage_sts_one(usm, st + (r + 4) * 256, av2[r]);
        }
        __syncthreads();

        if (t == Sn - 1 && kcCTA == 0 && tid < Hn)
            d_hfinal[b * Hn + tid] = hs[tid];   // row 0 (node 0)

        // reset x regions of both half buffers
        if (tid < 128)      ah0[(tid >> 3) * 80 + (tid & 7)] = 0.0f;
        else if (tid < 256) { int e = tid - 128; ah1[(e >> 3) * 80 + (e & 7)] = 0.0f; }

        b_barrier(b, (unsigned)(t + 1));
    }

    // ================= Readout =================
    g_barrier();
    if (kcCTA == 0 && b == 0) {
        float* hid = smem + SM_AH0;
        if (tid < Bn * (Hn / 2)) {
            int bb = tid / (Hn / 2);
            int u  = tid % (Hn / 2);
            float s = b1[u];
            #pragma unroll 8
            for (int k = 0; k < Hn; ++k)
                s += d_hfinal[bb * Hn + k] * W1[k * (Hn / 2) + u];
            hid[bb * (Hn / 2) + u] = fmaxf(s, 0.0f);
        }
        __syncthreads();
        if (tid < Bn * OUTn) {
            int bb = tid / OUTn;
            int o  = tid % OUTn;
            float s = b2[o];
            #pragma unroll
            for (int u = 0; u < Hn / 2; ++u)
                s += hid[bb * (Hn / 2) + u] * W2[u * OUTn + o];
            out[bb * OUTn + o] = s;
        }
    }
}

extern "C" void kernel_launch(void* const* d_in, const int* in_sizes, int n_in,
                              void* d_out, int out_size)
{
    const float* x   = (const float*)d_in[0];
    const float* adj = (const float*)d_in[1];
    const float* h0  = (const float*)d_in[2];
    const float* c0  = (const float*)d_in[3];
    const float* Wx  = (const float*)d_in[4];
    const float* Wh  = (const float*)d_in[5];
    const float* bg  = (const float*)d_in[6];
    const float* W1  = (const float*)d_in[7];
    const float* b1  = (const float*)d_in[8];
    const float* W2  = (const float*)d_in[9];
    const float* b2  = (const float*)d_in[10];
    float* out = (float*)d_out;

    cudaFuncSetAttribute(persistent_kernel,
                         cudaFuncAttributeMaxDynamicSharedMemorySize, SMEM_BYTES);

    init_kernel<<<(Sn * Bn * KC * 32 + 255) / 256, 256>>>(x, h0, Wx, Wh);

    dim3 grid(NTIL, Bn);   // 32 x 4 = 128 CTAs, single wave
    persistent_kernel<<<grid, TPB, SMEM_BYTES>>>(adj, c0, bg, W1, b1, W2, b2, out);
}